// round 11
// baseline (speedup 1.0000x reference)
#include <cuda_runtime.h>
#include <math.h>
#include <stdint.h>

#define NMAX 100000
#define EMAX 600000
#define HMAX 128

// Scratch (static __device__ arrays — allocation-free per harness rules)
__device__ float g_bufA[(size_t)NMAX * HMAX];
__device__ float g_bufB[(size_t)NMAX * HMAX];
__device__ int   g_deg[NMAX];
__device__ int   g_cnt[NMAX];
__device__ int   g_rowptr[NMAX + 1];
__device__ int   g_blocksums[(NMAX + 1023) / 1024 + 1];
__device__ float g_dinv[NMAX];
__device__ int   g_csrc[EMAX];   // CSR source index per edge (grouped by target)
__device__ float g_cw[EMAX];     // CSR edge weight (norm)

// ---------------------------------------------------------------------------
// CSR build (4 kernels total so ncu's 4th-launch capture hits csr_fill)
// ---------------------------------------------------------------------------
__global__ void count_deg_kernel(const int* __restrict__ col, int* deg, int E) {
    int e = blockIdx.x * blockDim.x + threadIdx.x;
    if (e < E) atomicAdd(&deg[col[e]], 1);
}

// Block-local exclusive scan of deg + per-block sums + dinv (fused)
__global__ void scan_block_kernel(const int* __restrict__ deg, int* excl,
                                  int* blocksums, float* __restrict__ dinv, int n) {
    __shared__ int sm[1024];
    int i = blockIdx.x * 1024 + threadIdx.x;
    int v = (i < n) ? deg[i] : 0;
    if (i < n) dinv[i] = rsqrtf((float)v + 1.0f);  // +1 self loop
    sm[threadIdx.x] = v;
    __syncthreads();
    for (int off = 1; off < 1024; off <<= 1) {
        int t = (threadIdx.x >= off) ? sm[threadIdx.x - off] : 0;
        __syncthreads();
        sm[threadIdx.x] += t;
        __syncthreads();
    }
    if (i < n) excl[i] = sm[threadIdx.x] - v;
    if (threadIdx.x == 1023) blocksums[blockIdx.x] = sm[1023];
}

// Finish: every block redundantly scans the (<=128) block sums in smem, then
// adds the prefix to its rowptr slice. Also zeroes cnt and sets rowptr[n]=E.
__global__ void scan_finish_kernel(int* rowptr, const int* __restrict__ blocksums,
                                   int* cnt, int nb, int n, int E) {
    __shared__ int sm[128];
    int v = (threadIdx.x < nb) ? blocksums[threadIdx.x] : 0;
    sm[threadIdx.x] = v;
    __syncthreads();
    for (int off = 1; off < 128; off <<= 1) {
        int t = (threadIdx.x >= off) ? sm[threadIdx.x - off] : 0;
        __syncthreads();
        sm[threadIdx.x] += t;
        __syncthreads();
    }
    // sm now holds inclusive scan; exclusive prefix of block b = sm[b] - bs[b]
    __syncthreads();
    int i = blockIdx.x * blockDim.x + threadIdx.x;
    if (i < n) {
        int b = i >> 10;
        rowptr[i] += sm[b] - blocksums[b];
        cnt[i] = 0;
    }
    if (i == 0) rowptr[n] = E;
}

__global__ void csr_fill_kernel(const int* __restrict__ row, const int* __restrict__ col,
                                const float* __restrict__ dinv, const int* __restrict__ rowptr,
                                int* cnt, int* __restrict__ csrc, float* __restrict__ cw, int E) {
    int e = blockIdx.x * blockDim.x + threadIdx.x;
    if (e >= E) return;
    int r = row[e], c = col[e];
    int pos = rowptr[c] + atomicAdd(&cnt[c], 1);
    csrc[pos] = r;
    cw[pos] = dinv[r] * dinv[c];
}

// ---------------------------------------------------------------------------
// CSR aggregation: out[i] = dinv[i]^2*h[i] + sum_e w[e]*h[src[e]]  (+bias)(relu)
// Each thread owns 8 floats (2 x float4); edge loop unrolled x2 with dual
// accumulators -> 4 independent LDG.128 in flight (MLP~4).
// ---------------------------------------------------------------------------
template <int D, bool BIAS, bool RELU>
__global__ void agg_csr_kernel(const float* __restrict__ h, const int* __restrict__ rp,
                               const int* __restrict__ src, const float* __restrict__ w,
                               const float* __restrict__ dinv, const float* __restrict__ bias,
                               float* __restrict__ out, int N) {
    constexpr int NV4 = D / 4;        // float4 slots per node
    constexpr int TPN = NV4 / 2;      // threads per node (2 float4 each)
    int tid = blockIdx.x * blockDim.x + threadIdx.x;
    int node = tid / TPN;
    int lane = tid - node * TPN;
    if (node >= N) return;
    int beg = rp[node], end = rp[node + 1];
    float di = dinv[node];
    float sw = di * di;
    const float4* hv = reinterpret_cast<const float4*>(h);
    size_t base = (size_t)node * NV4;
    float4 s0 = hv[base + lane];
    float4 s1 = hv[base + lane + TPN];
    float4 a0 = make_float4(sw * s0.x, sw * s0.y, sw * s0.z, sw * s0.w);
    float4 a1 = make_float4(sw * s1.x, sw * s1.y, sw * s1.z, sw * s1.w);
    float4 b0 = make_float4(0.f, 0.f, 0.f, 0.f);
    float4 b1 = make_float4(0.f, 0.f, 0.f, 0.f);
    int e = beg;
    for (; e + 1 < end; e += 2) {
        int sA = src[e], sB = src[e + 1];
        float wA = w[e], wB = w[e + 1];
        size_t pA = (size_t)sA * NV4 + lane;
        size_t pB = (size_t)sB * NV4 + lane;
        float4 vA0 = hv[pA], vA1 = hv[pA + TPN];
        float4 vB0 = hv[pB], vB1 = hv[pB + TPN];
        a0.x += wA * vA0.x; a0.y += wA * vA0.y; a0.z += wA * vA0.z; a0.w += wA * vA0.w;
        a1.x += wA * vA1.x; a1.y += wA * vA1.y; a1.z += wA * vA1.z; a1.w += wA * vA1.w;
        b0.x += wB * vB0.x; b0.y += wB * vB0.y; b0.z += wB * vB0.z; b0.w += wB * vB0.w;
        b1.x += wB * vB1.x; b1.y += wB * vB1.y; b1.z += wB * vB1.z; b1.w += wB * vB1.w;
    }
    if (e < end) {
        int sA = src[e];
        float wA = w[e];
        size_t pA = (size_t)sA * NV4 + lane;
        float4 vA0 = hv[pA], vA1 = hv[pA + TPN];
        a0.x += wA * vA0.x; a0.y += wA * vA0.y; a0.z += wA * vA0.z; a0.w += wA * vA0.w;
        a1.x += wA * vA1.x; a1.y += wA * vA1.y; a1.z += wA * vA1.z; a1.w += wA * vA1.w;
    }
    a0.x += b0.x; a0.y += b0.y; a0.z += b0.z; a0.w += b0.w;
    a1.x += b1.x; a1.y += b1.y; a1.z += b1.z; a1.w += b1.w;
    if (BIAS) {
        float4 c0 = reinterpret_cast<const float4*>(bias)[lane];
        float4 c1 = reinterpret_cast<const float4*>(bias)[lane + TPN];
        a0.x += c0.x; a0.y += c0.y; a0.z += c0.z; a0.w += c0.w;
        a1.x += c1.x; a1.y += c1.y; a1.z += c1.z; a1.w += c1.w;
    }
    if (RELU) {
        a0.x = fmaxf(a0.x, 0.f); a0.y = fmaxf(a0.y, 0.f);
        a0.z = fmaxf(a0.z, 0.f); a0.w = fmaxf(a0.w, 0.f);
        a1.x = fmaxf(a1.x, 0.f); a1.y = fmaxf(a1.y, 0.f);
        a1.z = fmaxf(a1.z, 0.f); a1.w = fmaxf(a1.w, 0.f);
    }
    float4* ov = reinterpret_cast<float4*>(out);
    ov[base + lane] = a0;
    ov[base + lane + TPN] = a1;
}

// D=1 aggregation (+scalar bias) for the final layer
__global__ void agg_csr1_kernel(const float* __restrict__ h, const int* __restrict__ rp,
                                const int* __restrict__ src, const float* __restrict__ w,
                                const float* __restrict__ dinv, const float* __restrict__ bias,
                                float* __restrict__ out, int N) {
    int i = blockIdx.x * blockDim.x + threadIdx.x;
    if (i >= N) return;
    float di = dinv[i];
    float accA = di * di * h[i], accB = 0.f;
    int beg = rp[i], end = rp[i + 1];
    int e = beg;
    for (; e + 1 < end; e += 2) {
        accA += w[e] * h[src[e]];
        accB += w[e + 1] * h[src[e + 1]];
    }
    if (e < end) accA += w[e] * h[src[e]];
    out[i] = accA + accB + bias[0];
}

// ---------------------------------------------------------------------------
// Fused L1: warp per node. All 32 lanes redundantly compute the D=3
// aggregation (broadcast loads), then each lane emits 4 of 128 output cols:
// out = relu(agg3(x) @ W1 + b1).
// ---------------------------------------------------------------------------
__global__ void l1_fused_kernel(const float* __restrict__ x, const int* __restrict__ rp,
                                const int* __restrict__ src, const float* __restrict__ w,
                                const float* __restrict__ dinv, const float* __restrict__ W,
                                const float* __restrict__ bias, float* __restrict__ out, int N) {
    int tid = blockIdx.x * blockDim.x + threadIdx.x;
    int node = tid >> 5;
    int c4 = (tid & 31) * 4;
    if (node >= N) return;
    float di = dinv[node];
    float sw = di * di;
    float a0 = sw * x[(size_t)node * 3 + 0];
    float a1 = sw * x[(size_t)node * 3 + 1];
    float a2 = sw * x[(size_t)node * 3 + 2];
    int beg = rp[node], end = rp[node + 1];
    for (int e = beg; e < end; e++) {
        int s = src[e];
        float ww = w[e];
        a0 += ww * x[(size_t)s * 3 + 0];
        a1 += ww * x[(size_t)s * 3 + 1];
        a2 += ww * x[(size_t)s * 3 + 2];
    }
    float4 w0 = *reinterpret_cast<const float4*>(W + 0 * 128 + c4);
    float4 w1 = *reinterpret_cast<const float4*>(W + 1 * 128 + c4);
    float4 w2 = *reinterpret_cast<const float4*>(W + 2 * 128 + c4);
    float4 b  = *reinterpret_cast<const float4*>(bias + c4);
    float4 v;
    v.x = fmaxf(a0 * w0.x + a1 * w1.x + a2 * w2.x + b.x, 0.f);
    v.y = fmaxf(a0 * w0.y + a1 * w1.y + a2 * w2.y + b.y, 0.f);
    v.z = fmaxf(a0 * w0.z + a1 * w1.z + a2 * w2.z + b.z, 0.f);
    v.w = fmaxf(a0 * w0.w + a1 * w1.w + a2 * w2.w + b.w, 0.f);
    *reinterpret_cast<float4*>(out + (size_t)node * 128 + c4) = v;
}

// ---------------------------------------------------------------------------
// TF32 tensor-core GEMM: C[N,M] = A[N,K] @ W[K,M]  (raw output; bias/relu
// fused into the following aggregation pass). BM=128, BK=32, 8 warps.
// ---------------------------------------------------------------------------
__device__ __forceinline__ uint32_t f2tf32(float f) {
    uint32_t r;
    asm("cvt.rna.tf32.f32 %0, %1;" : "=r"(r) : "f"(f));
    return r;
}

__device__ __forceinline__ void mma_tf32(float* d, const uint32_t* a, const uint32_t* b) {
    asm volatile(
        "mma.sync.aligned.m16n8k8.row.col.f32.tf32.tf32.f32 "
        "{%0,%1,%2,%3},{%4,%5,%6,%7},{%8,%9},{%0,%1,%2,%3};"
        : "+f"(d[0]), "+f"(d[1]), "+f"(d[2]), "+f"(d[3])
        : "r"(a[0]), "r"(a[1]), "r"(a[2]), "r"(a[3]), "r"(b[0]), "r"(b[1]));
}

template <int BN, int MW, int NW>
__global__ __launch_bounds__(256) void gemm_tf32_kernel(
    const float* __restrict__ A, const float* __restrict__ W,
    float* __restrict__ C, int N, int K, int M) {
    constexpr int BM = 128, BK = 32;
    constexpr int WMT = BM / MW;       // warp tile M
    constexpr int WNT = BN / NW;       // warp tile N
    constexpr int MF = WMT / 16, NF = WNT / 8;
    constexpr int LDS = BK + 4;        // padded row (words)

    __shared__ uint32_t As[BM * LDS];  // As[m][k], tf32
    __shared__ uint32_t Bs[BN * LDS];  // Bs[n][k] = W[k][n], tf32

    int tid = threadIdx.x;
    int wid = tid >> 5, lane = tid & 31;
    int wm = wid / NW, wn = wid % NW;
    int row0 = blockIdx.y * BM, col0 = blockIdx.x * BN;

    float acc[MF][NF][4] = {};

    for (int k0 = 0; k0 < K; k0 += BK) {
        // ---- A tile: BM x BK, float4 along k ----
#pragma unroll
        for (int t = 0; t < 4; t++) {
            int i = tid + t * 256;         // 0..1023
            int r = i >> 3;
            int kq = i & 7;
            int gr = row0 + r;
            float4 v = make_float4(0.f, 0.f, 0.f, 0.f);
            if (gr < N) v = *reinterpret_cast<const float4*>(A + (size_t)gr * K + k0 + kq * 4);
            uint32_t* dst = &As[r * LDS + kq * 4];
            dst[0] = f2tf32(v.x); dst[1] = f2tf32(v.y);
            dst[2] = f2tf32(v.z); dst[3] = f2tf32(v.w);
        }
        // ---- W tile: BK x BN, transpose into Bs[n][k] ----
        constexpr int QB = BK * BN / 4 / 256;
#pragma unroll
        for (int t = 0; t < QB; t++) {
            int i = tid + t * 256;
            int r = i / (BN / 4);          // k in [0,32)
            int cq = i % (BN / 4);
            float4 v = *reinterpret_cast<const float4*>(W + (size_t)(k0 + r) * M + col0 + cq * 4);
            Bs[(cq * 4 + 0) * LDS + r] = f2tf32(v.x);
            Bs[(cq * 4 + 1) * LDS + r] = f2tf32(v.y);
            Bs[(cq * 4 + 2) * LDS + r] = f2tf32(v.z);
            Bs[(cq * 4 + 3) * LDS + r] = f2tf32(v.w);
        }
        __syncthreads();

#pragma unroll
        for (int kk = 0; kk < BK; kk += 8) {
            uint32_t af[MF][4], bf[NF][2];
            int c = kk + (lane & 3);
            int rq = lane >> 2;
#pragma unroll
            for (int mi = 0; mi < MF; mi++) {
                int r = wm * WMT + mi * 16 + rq;
                af[mi][0] = As[r * LDS + c];
                af[mi][1] = As[(r + 8) * LDS + c];
                af[mi][2] = As[r * LDS + c + 4];
                af[mi][3] = As[(r + 8) * LDS + c + 4];
            }
#pragma unroll
            for (int ni = 0; ni < NF; ni++) {
                int n = wn * WNT + ni * 8 + rq;
                bf[ni][0] = Bs[n * LDS + c];
                bf[ni][1] = Bs[n * LDS + c + 4];
            }
#pragma unroll
            for (int mi = 0; mi < MF; mi++)
#pragma unroll
                for (int ni = 0; ni < NF; ni++)
                    mma_tf32(acc[mi][ni], af[mi], bf[ni]);
        }
        __syncthreads();
    }

    // ---- epilogue ----
#pragma unroll
    for (int mi = 0; mi < MF; mi++) {
        int r_lo = row0 + wm * WMT + mi * 16 + (lane >> 2);
#pragma unroll
        for (int ni = 0; ni < NF; ni++) {
            int gc = col0 + wn * WNT + ni * 8 + 2 * (lane & 3);
            if (r_lo < N)
                *reinterpret_cast<float2*>(C + (size_t)r_lo * M + gc) =
                    make_float2(acc[mi][ni][0], acc[mi][ni][1]);
            if (r_lo + 8 < N)
                *reinterpret_cast<float2*>(C + (size_t)(r_lo + 8) * M + gc) =
                    make_float2(acc[mi][ni][2], acc[mi][ni][3]);
        }
    }
}

// M=1 GEMV (layer 5): warp per row, shuffle reduce.
__global__ void gemv_kernel(const float* __restrict__ A, const float* __restrict__ w,
                            float* __restrict__ out, int N, int K) {
    int warp = (blockIdx.x * blockDim.x + threadIdx.x) / 32;
    int lane = threadIdx.x % 32;
    if (warp >= N) return;
    float acc = 0.0f;
    for (int k = lane; k < K; k += 32) acc += A[(size_t)warp * K + k] * w[k];
#pragma unroll
    for (int off = 16; off > 0; off >>= 1) acc += __shfl_down_sync(0xffffffffu, acc, off);
    if (lane == 0) out[warp] = acc;
}

// ---------------------------------------------------------------------------
// Launch
// ---------------------------------------------------------------------------
extern "C" void kernel_launch(void* const* d_in, const int* in_sizes, int n_in,
                              void* d_out, int out_size) {
    const float* x  = (const float*)d_in[0];
    const int*   ei = (const int*)d_in[1];
    const float* W1 = (const float*)d_in[2];
    const float* b1 = (const float*)d_in[3];
    const float* W2 = (const float*)d_in[4];
    const float* b2 = (const float*)d_in[5];
    const float* W3 = (const float*)d_in[6];
    const float* b3 = (const float*)d_in[7];
    const float* W4 = (const float*)d_in[8];
    const float* b4 = (const float*)d_in[9];
    const float* W5 = (const float*)d_in[10];
    const float* b5 = (const float*)d_in[11];

    int N = in_sizes[0] / 3;
    int E = in_sizes[1] / 2;
    const int* row = ei;       // sources (gather index)
    const int* col = ei + E;   // targets (aggregation index)

    float *bufA, *bufB, *dinv, *cw;
    int *deg, *cnt, *rowptr, *blocksums, *csrc;
    cudaGetSymbolAddress((void**)&bufA, g_bufA);
    cudaGetSymbolAddress((void**)&bufB, g_bufB);
    cudaGetSymbolAddress((void**)&deg, g_deg);
    cudaGetSymbolAddress((void**)&cnt, g_cnt);
    cudaGetSymbolAddress((void**)&rowptr, g_rowptr);
    cudaGetSymbolAddress((void**)&blocksums, g_blocksums);
    cudaGetSymbolAddress((void**)&dinv, g_dinv);
    cudaGetSymbolAddress((void**)&csrc, g_csrc);
    cudaGetSymbolAddress((void**)&cw, g_cw);

    const int T = 256;
    auto cdiv = [](long long a, long long b) { return (int)((a + b - 1) / b); };
    int nb = cdiv(N, 1024);

    // ---- CSR build (4 kernels; ncu's 4th-launch capture lands on csr_fill) ----
    cudaMemsetAsync(deg, 0, (size_t)N * sizeof(int));
    count_deg_kernel<<<cdiv(E, T), T>>>(col, deg, E);
    scan_block_kernel<<<nb, 1024>>>(deg, rowptr, blocksums, dinv, N);
    scan_finish_kernel<<<cdiv(N, 128), 128>>>(rowptr, blocksums, cnt, nb, N, E);
    csr_fill_kernel<<<cdiv(E, T), T>>>(row, col, dinv, rowptr, cnt, csrc, cw, E);

    // ---- L1 fused: agg(x)[D=3] @ W1 + b1, relu ----
    l1_fused_kernel<<<cdiv((long long)N * 32, T), T>>>(x, rowptr, csrc, cw, dinv, W1, b1, bufB, N);

    // ---- L2: TF32 GEMM 128->128, then agg (+b2, relu) ----
    {
        dim3 g(1, cdiv(N, 128));
        gemm_tf32_kernel<128, 2, 4><<<g, T>>>(bufB, W2, bufA, N, 128, 128);
    }
    agg_csr_kernel<128, true, true><<<cdiv((long long)N * 16, T), T>>>(
        bufA, rowptr, csrc, cw, dinv, b2, bufB, N);

    // ---- L3: TF32 GEMM 128->64, then agg (+b3, relu) ----
    {
        dim3 g(1, cdiv(N, 128));
        gemm_tf32_kernel<64, 4, 2><<<g, T>>>(bufB, W3, bufA, N, 128, 64);
    }
    agg_csr_kernel<64, true, true><<<cdiv((long long)N * 8, T), T>>>(
        bufA, rowptr, csrc, cw, dinv, b3, bufB, N);

    // ---- L4: TF32 GEMM 64->64, then agg (+b4, relu) ----
    {
        dim3 g(1, cdiv(N, 128));
        gemm_tf32_kernel<64, 4, 2><<<g, T>>>(bufB, W4, bufA, N, 64, 64);
    }
    agg_csr_kernel<64, true, true><<<cdiv((long long)N * 8, T), T>>>(
        bufA, rowptr, csrc, cw, dinv, b4, bufB, N);

    // ---- L5: GEMV 64->1, then agg (+b5) into d_out ----
    gemv_kernel<<<cdiv((long long)N * 32, T), T>>>(bufB, W5, bufA, N, 64);
    agg_csr1_kernel<<<cdiv(N, T), T>>>(bufA, rowptr, csrc, cw, dinv, b5, (float*)d_out, N);
}

// round 14
// speedup vs baseline: 1.2925x; 1.2925x over previous
#include <cuda_runtime.h>
#include <cuda_fp16.h>
#include <math.h>
#include <stdint.h>

#define NMAX 100000
#define EMAX 600000
#define HMAX 128

// Scratch (static __device__ arrays — allocation-free per harness rules)
__device__ __half g_hA[(size_t)NMAX * HMAX];
__device__ __half g_hB[(size_t)NMAX * HMAX];
__device__ float  g_s1[NMAX];
__device__ int    g_deg[NMAX];
__device__ int    g_cnt[NMAX];
__device__ int    g_rowptr[NMAX + 1];
__device__ int    g_blocksums[(NMAX + 1023) / 1024 + 1];
__device__ float  g_dinv[NMAX];
__device__ int    g_csrc[EMAX];   // CSR source index per edge (grouped by target)
__device__ float  g_cw[EMAX];     // CSR edge weight (norm)

// ---------------------------------------------------------------------------
// CSR build
// ---------------------------------------------------------------------------
__global__ void count_deg_kernel(const int* __restrict__ col, int* deg, int E) {
    int e = blockIdx.x * blockDim.x + threadIdx.x;
    if (e < E) atomicAdd(&deg[col[e]], 1);
}

// Block-local exclusive scan of deg + per-block sums + dinv (fused)
__global__ void scan_block_kernel(const int* __restrict__ deg, int* excl,
                                  int* blocksums, float* __restrict__ dinv, int n) {
    __shared__ int sm[1024];
    int i = blockIdx.x * 1024 + threadIdx.x;
    int v = (i < n) ? deg[i] : 0;
    if (i < n) dinv[i] = rsqrtf((float)v + 1.0f);  // +1 self loop
    sm[threadIdx.x] = v;
    __syncthreads();
    for (int off = 1; off < 1024; off <<= 1) {
        int t = (threadIdx.x >= off) ? sm[threadIdx.x - off] : 0;
        __syncthreads();
        sm[threadIdx.x] += t;
        __syncthreads();
    }
    if (i < n) excl[i] = sm[threadIdx.x] - v;
    if (threadIdx.x == 1023) blocksums[blockIdx.x] = sm[1023];
}

// Finish: every block redundantly scans the (<=128) block sums in smem, adds
// the prefix to its rowptr slice, and seeds cnt with the final start offset
// (so csr_fill atomics directly on cnt with no rowptr gather).
__global__ void scan_finish_kernel(int* rowptr, const int* __restrict__ blocksums,
                                   int* cnt, int nb, int n, int E) {
    __shared__ int sm[128];
    int v = (threadIdx.x < nb) ? blocksums[threadIdx.x] : 0;
    sm[threadIdx.x] = v;
    __syncthreads();
    for (int off = 1; off < 128; off <<= 1) {
        int t = (threadIdx.x >= off) ? sm[threadIdx.x - off] : 0;
        __syncthreads();
        sm[threadIdx.x] += t;
        __syncthreads();
    }
    __syncthreads();
    int i = blockIdx.x * blockDim.x + threadIdx.x;
    if (i < n) {
        int b = i >> 10;
        int start = rowptr[i] + sm[b] - blocksums[b];
        rowptr[i] = start;
        cnt[i] = start;
    }
    if (i == 0) rowptr[n] = E;
}

__global__ void csr_fill_kernel(const int* __restrict__ row, const int* __restrict__ col,
                                const float* __restrict__ dinv,
                                int* cnt, int* __restrict__ csrc, float* __restrict__ cw, int E) {
    int e = blockIdx.x * blockDim.x + threadIdx.x;
    if (e >= E) return;
    int r = row[e], c = col[e];
    int pos = atomicAdd(&cnt[c], 1);
    csrc[pos] = r;
    cw[pos] = dinv[r] * dinv[c];
}

// ---------------------------------------------------------------------------
// fp16 CSR aggregation: out[i] = dinv^2*h[i] + sum_e w[e]*h[src[e]] (+bias)(relu)
// Each thread owns 8 halfs (one uint4); fp32 accumulation; edge loop x2
// unrolled with dual accumulators.
// ---------------------------------------------------------------------------
template <int D>
__global__ void agg_csr_h_kernel(const __half* __restrict__ h, const int* __restrict__ rp,
                                 const int* __restrict__ src, const float* __restrict__ w,
                                 const float* __restrict__ dinv, const float* __restrict__ bias,
                                 __half* __restrict__ out, int N) {
    constexpr int TPN = D / 8;        // threads per node (8 halfs each)
    int tid = blockIdx.x * blockDim.x + threadIdx.x;
    int node = tid / TPN;
    int lane = tid - node * TPN;
    if (node >= N) return;
    int beg = rp[node], end = rp[node + 1];
    float di = dinv[node];
    float sw = di * di;
    const uint4* hv = reinterpret_cast<const uint4*>(h);
    size_t base = (size_t)node * TPN + lane;

    float2 accA[4], accB[4];
    {
        uint4 u = hv[base];
        const __half2* hp = reinterpret_cast<const __half2*>(&u);
#pragma unroll
        for (int j = 0; j < 4; j++) {
            float2 f = __half22float2(hp[j]);
            accA[j] = make_float2(sw * f.x, sw * f.y);
            accB[j] = make_float2(0.f, 0.f);
        }
    }
    int e = beg;
    for (; e + 1 < end; e += 2) {
        int sA = src[e], sB = src[e + 1];
        float wA = w[e], wB = w[e + 1];
        uint4 uA = hv[(size_t)sA * TPN + lane];
        uint4 uB = hv[(size_t)sB * TPN + lane];
        const __half2* hA = reinterpret_cast<const __half2*>(&uA);
        const __half2* hB = reinterpret_cast<const __half2*>(&uB);
#pragma unroll
        for (int j = 0; j < 4; j++) {
            float2 fA = __half22float2(hA[j]);
            float2 fB = __half22float2(hB[j]);
            accA[j].x += wA * fA.x; accA[j].y += wA * fA.y;
            accB[j].x += wB * fB.x; accB[j].y += wB * fB.y;
        }
    }
    if (e < end) {
        int sA = src[e];
        float wA = w[e];
        uint4 uA = hv[(size_t)sA * TPN + lane];
        const __half2* hA = reinterpret_cast<const __half2*>(&uA);
#pragma unroll
        for (int j = 0; j < 4; j++) {
            float2 fA = __half22float2(hA[j]);
            accA[j].x += wA * fA.x; accA[j].y += wA * fA.y;
        }
    }
    const float4* bv = reinterpret_cast<const float4*>(bias);
    float4 b0 = bv[lane * 2 + 0];
    float4 b1 = bv[lane * 2 + 1];
    float bb[8] = {b0.x, b0.y, b0.z, b0.w, b1.x, b1.y, b1.z, b1.w};
    uint4 o;
    __half2* op = reinterpret_cast<__half2*>(&o);
#pragma unroll
    for (int j = 0; j < 4; j++) {
        float vx = fmaxf(accA[j].x + accB[j].x + bb[2 * j + 0], 0.f);
        float vy = fmaxf(accA[j].y + accB[j].y + bb[2 * j + 1], 0.f);
        op[j] = __floats2half2_rn(vx, vy);
    }
    reinterpret_cast<uint4*>(out)[base] = o;
}

// D=1 aggregation (+scalar bias) for the final layer (fp32 in/out)
__global__ void agg_csr1_kernel(const float* __restrict__ h, const int* __restrict__ rp,
                                const int* __restrict__ src, const float* __restrict__ w,
                                const float* __restrict__ dinv, const float* __restrict__ bias,
                                float* __restrict__ out, int N) {
    int i = blockIdx.x * blockDim.x + threadIdx.x;
    if (i >= N) return;
    float di = dinv[i];
    float accA = di * di * h[i], accB = 0.f;
    int beg = rp[i], end = rp[i + 1];
    int e = beg;
    for (; e + 1 < end; e += 2) {
        accA += w[e] * h[src[e]];
        accB += w[e + 1] * h[src[e + 1]];
    }
    if (e < end) accA += w[e] * h[src[e]];
    out[i] = accA + accB + bias[0];
}

// ---------------------------------------------------------------------------
// Fused L1: warp per node. All 32 lanes redundantly compute the D=3
// aggregation (broadcast loads), each lane emits 4 of 128 output cols as fp16:
// out = relu(agg3(x) @ W1 + b1).
// ---------------------------------------------------------------------------
__global__ void l1_fused_kernel(const float* __restrict__ x, const int* __restrict__ rp,
                                const int* __restrict__ src, const float* __restrict__ w,
                                const float* __restrict__ dinv, const float* __restrict__ W,
                                const float* __restrict__ bias, __half* __restrict__ out, int N) {
    int tid = blockIdx.x * blockDim.x + threadIdx.x;
    int node = tid >> 5;
    int c4 = (tid & 31) * 4;
    if (node >= N) return;
    float di = dinv[node];
    float sw = di * di;
    float a0 = sw * x[(size_t)node * 3 + 0];
    float a1 = sw * x[(size_t)node * 3 + 1];
    float a2 = sw * x[(size_t)node * 3 + 2];
    int beg = rp[node], end = rp[node + 1];
    for (int e = beg; e < end; e++) {
        int s = src[e];
        float ww = w[e];
        a0 += ww * x[(size_t)s * 3 + 0];
        a1 += ww * x[(size_t)s * 3 + 1];
        a2 += ww * x[(size_t)s * 3 + 2];
    }
    float4 w0 = *reinterpret_cast<const float4*>(W + 0 * 128 + c4);
    float4 w1 = *reinterpret_cast<const float4*>(W + 1 * 128 + c4);
    float4 w2 = *reinterpret_cast<const float4*>(W + 2 * 128 + c4);
    float4 b  = *reinterpret_cast<const float4*>(bias + c4);
    float vx = fmaxf(a0 * w0.x + a1 * w1.x + a2 * w2.x + b.x, 0.f);
    float vy = fmaxf(a0 * w0.y + a1 * w1.y + a2 * w2.y + b.y, 0.f);
    float vz = fmaxf(a0 * w0.z + a1 * w1.z + a2 * w2.z + b.z, 0.f);
    float vw = fmaxf(a0 * w0.w + a1 * w1.w + a2 * w2.w + b.w, 0.f);
    __half2 h0 = __floats2half2_rn(vx, vy);
    __half2 h1 = __floats2half2_rn(vz, vw);
    uint2 o;
    o.x = *reinterpret_cast<unsigned int*>(&h0);
    o.y = *reinterpret_cast<unsigned int*>(&h1);
    *reinterpret_cast<uint2*>(out + (size_t)node * 128 + c4) = o;
}

// ---------------------------------------------------------------------------
// fp16 tensor-core GEMM: C[N,M] = A[N,K] @ W[K,M], A/C fp16, W fp32->fp16.
// BM=128, BK=32, 256 threads (8 warps), mma.sync.m16n8k16.f16 with fp32 acc.
// Raw output; bias/relu fused into the following aggregation pass.
// ---------------------------------------------------------------------------
__device__ __forceinline__ void mma_f16(float* d, const uint32_t* a, const uint32_t* b) {
    asm volatile(
        "mma.sync.aligned.m16n8k16.row.col.f32.f16.f16.f32 "
        "{%0,%1,%2,%3},{%4,%5,%6,%7},{%8,%9},{%0,%1,%2,%3};"
        : "+f"(d[0]), "+f"(d[1]), "+f"(d[2]), "+f"(d[3])
        : "r"(a[0]), "r"(a[1]), "r"(a[2]), "r"(a[3]), "r"(b[0]), "r"(b[1]));
}

template <int BN, int MW, int NW>
__global__ __launch_bounds__(256) void gemm_f16_kernel(
    const __half* __restrict__ A, const float* __restrict__ W,
    __half* __restrict__ C, int N, int K, int M) {
    constexpr int BM = 128, BK = 32;
    constexpr int WMT = BM / MW;       // warp tile M
    constexpr int WNT = BN / NW;       // warp tile N
    constexpr int MF = WMT / 16, NF = WNT / 8;
    constexpr int LDSH = BK + 8;       // padded row (halfs): 40 halfs = 80 B

    __shared__ __half As[BM * LDSH];   // As[m][k]
    __shared__ __half Bs[BN * LDSH];   // Bs[n][k] = W[k][n]

    int tid = threadIdx.x;
    int wid = tid >> 5, lane = tid & 31;
    int wm = wid / NW, wn = wid % NW;
    int row0 = blockIdx.y * BM, col0 = blockIdx.x * BN;

    float acc[MF][NF][4] = {};

    for (int k0 = 0; k0 < K; k0 += BK) {
        // ---- A tile: BM x BK halfs, uint4 = 8 halfs per load ----
#pragma unroll
        for (int t = 0; t < 2; t++) {
            int i = tid + t * 256;          // 0..511
            int r = i >> 2;
            int kq = i & 3;
            int gr = row0 + r;
            uint4 v = make_uint4(0u, 0u, 0u, 0u);
            if (gr < N) v = *reinterpret_cast<const uint4*>(A + (size_t)gr * K + k0 + kq * 8);
            *reinterpret_cast<uint4*>(&As[r * LDSH + kq * 8]) = v;
        }
        // ---- W tile: BK x BN fp32 -> Bs[n][k] fp16 (transpose) ----
        constexpr int QB = BK * BN / 4 / 256;
#pragma unroll
        for (int t = 0; t < QB; t++) {
            int i = tid + t * 256;
            int r = i / (BN / 4);           // k in [0,32)
            int cq = i % (BN / 4);
            float4 v = *reinterpret_cast<const float4*>(W + (size_t)(k0 + r) * M + col0 + cq * 4);
            Bs[(cq * 4 + 0) * LDSH + r] = __float2half(v.x);
            Bs[(cq * 4 + 1) * LDSH + r] = __float2half(v.y);
            Bs[(cq * 4 + 2) * LDSH + r] = __float2half(v.z);
            Bs[(cq * 4 + 3) * LDSH + r] = __float2half(v.w);
        }
        __syncthreads();

#pragma unroll
        for (int kk = 0; kk < BK; kk += 16) {
            uint32_t af[MF][4], bf[NF][2];
            int c = kk + 2 * (lane & 3);
            int rq = lane >> 2;
#pragma unroll
            for (int mi = 0; mi < MF; mi++) {
                int r = wm * WMT + mi * 16 + rq;
                af[mi][0] = *reinterpret_cast<const uint32_t*>(&As[r * LDSH + c]);
                af[mi][1] = *reinterpret_cast<const uint32_t*>(&As[(r + 8) * LDSH + c]);
                af[mi][2] = *reinterpret_cast<const uint32_t*>(&As[r * LDSH + c + 8]);
                af[mi][3] = *reinterpret_cast<const uint32_t*>(&As[(r + 8) * LDSH + c + 8]);
            }
#pragma unroll
            for (int ni = 0; ni < NF; ni++) {
                int n = wn * WNT + ni * 8 + rq;
                bf[ni][0] = *reinterpret_cast<const uint32_t*>(&Bs[n * LDSH + c]);
                bf[ni][1] = *reinterpret_cast<const uint32_t*>(&Bs[n * LDSH + c + 8]);
            }
#pragma unroll
            for (int mi = 0; mi < MF; mi++)
#pragma unroll
                for (int ni = 0; ni < NF; ni++)
                    mma_f16(acc[mi][ni], af[mi], bf[ni]);
        }
        __syncthreads();
    }

    // ---- epilogue: fp32 acc -> fp16 pairs ----
#pragma unroll
    for (int mi = 0; mi < MF; mi++) {
        int r_lo = row0 + wm * WMT + mi * 16 + (lane >> 2);
#pragma unroll
        for (int ni = 0; ni < NF; ni++) {
            int gc = col0 + wn * WNT + ni * 8 + 2 * (lane & 3);
            if (r_lo < N) {
                __half2 h = __floats2half2_rn(acc[mi][ni][0], acc[mi][ni][1]);
                *reinterpret_cast<uint32_t*>(C + (size_t)r_lo * M + gc) =
                    *reinterpret_cast<uint32_t*>(&h);
            }
            if (r_lo + 8 < N) {
                __half2 h = __floats2half2_rn(acc[mi][ni][2], acc[mi][ni][3]);
                *reinterpret_cast<uint32_t*>(C + (size_t)(r_lo + 8) * M + gc) =
                    *reinterpret_cast<uint32_t*>(&h);
            }
        }
    }
}

// M=1 GEMV (layer 5): warp per row, fp16 input, shuffle reduce, fp32 out.
__global__ void gemv_kernel(const __half* __restrict__ A, const float* __restrict__ w,
                            float* __restrict__ out, int N, int K) {
    int warp = (blockIdx.x * blockDim.x + threadIdx.x) / 32;
    int lane = threadIdx.x % 32;
    if (warp >= N) return;
    float acc = 0.0f;
    for (int k2 = lane; k2 * 2 < K; k2 += 32) {
        __half2 h = *reinterpret_cast<const __half2*>(A + (size_t)warp * K + k2 * 2);
        float2 f = __half22float2(h);
        acc += f.x * w[k2 * 2] + f.y * w[k2 * 2 + 1];
    }
#pragma unroll
    for (int off = 16; off > 0; off >>= 1) acc += __shfl_down_sync(0xffffffffu, acc, off);
    if (lane == 0) out[warp] = acc;
}

// ---------------------------------------------------------------------------
// Launch
// ---------------------------------------------------------------------------
extern "C" void kernel_launch(void* const* d_in, const int* in_sizes, int n_in,
                              void* d_out, int out_size) {
    const float* x  = (const float*)d_in[0];
    const int*   ei = (const int*)d_in[1];
    const float* W1 = (const float*)d_in[2];
    const float* b1 = (const float*)d_in[3];
    const float* W2 = (const float*)d_in[4];
    const float* b2 = (const float*)d_in[5];
    const float* W3 = (const float*)d_in[6];
    const float* b3 = (const float*)d_in[7];
    const float* W4 = (const float*)d_in[8];
    const float* b4 = (const float*)d_in[9];
    const float* W5 = (const float*)d_in[10];
    const float* b5 = (const float*)d_in[11];

    int N = in_sizes[0] / 3;
    int E = in_sizes[1] / 2;
    const int* row = ei;       // sources (gather index)
    const int* col = ei + E;   // targets (aggregation index)

    __half *hA, *hB;
    float *s1, *dinv, *cw;
    int *deg, *cnt, *rowptr, *blocksums, *csrc;
    cudaGetSymbolAddress((void**)&hA, g_hA);
    cudaGetSymbolAddress((void**)&hB, g_hB);
    cudaGetSymbolAddress((void**)&s1, g_s1);
    cudaGetSymbolAddress((void**)&deg, g_deg);
    cudaGetSymbolAddress((void**)&cnt, g_cnt);
    cudaGetSymbolAddress((void**)&rowptr, g_rowptr);
    cudaGetSymbolAddress((void**)&blocksums, g_blocksums);
    cudaGetSymbolAddress((void**)&dinv, g_dinv);
    cudaGetSymbolAddress((void**)&csrc, g_csrc);
    cudaGetSymbolAddress((void**)&cw, g_cw);

    const int T = 256;
    auto cdiv = [](long long a, long long b) { return (int)((a + b - 1) / b); };
    int nb = cdiv(N, 1024);

    // ---- CSR build ----
    cudaMemsetAsync(deg, 0, (size_t)N * sizeof(int));
    count_deg_kernel<<<cdiv(E, T), T>>>(col, deg, E);
    scan_block_kernel<<<nb, 1024>>>(deg, rowptr, blocksums, dinv, N);
    scan_finish_kernel<<<cdiv(N, 128), 128>>>(rowptr, blocksums, cnt, nb, N, E);
    csr_fill_kernel<<<cdiv(E, T), T>>>(row, col, dinv, cnt, csrc, cw, E);

    // ---- L1 fused: agg(x)[D=3] @ W1 + b1, relu -> fp16 ----
    l1_fused_kernel<<<cdiv((long long)N * 32, T), T>>>(x, rowptr, csrc, cw, dinv, W1, b1, hB, N);

    // ---- L2: fp16 GEMM 128->128, then agg (+b2, relu) ----
    {
        dim3 g(1, cdiv(N, 128));
        gemm_f16_kernel<128, 2, 4><<<g, T>>>(hB, W2, hA, N, 128, 128);
    }
    agg_csr_h_kernel<128><<<cdiv((long long)N * 16, T), T>>>(
        hA, rowptr, csrc, cw, dinv, b2, hB, N);

    // ---- L3: fp16 GEMM 128->64, then agg (+b3, relu) ----
    {
        dim3 g(1, cdiv(N, 128));
        gemm_f16_kernel<64, 4, 2><<<g, T>>>(hB, W3, hA, N, 128, 64);
    }
    agg_csr_h_kernel<64><<<cdiv((long long)N * 8, T), T>>>(
        hA, rowptr, csrc, cw, dinv, b3, hB, N);

    // ---- L4: fp16 GEMM 64->64, then agg (+b4, relu) ----
    {
        dim3 g(1, cdiv(N, 128));
        gemm_f16_kernel<64, 4, 2><<<g, T>>>(hB, W4, hA, N, 64, 64);
    }
    agg_csr_h_kernel<64><<<cdiv((long long)N * 8, T), T>>>(
        hA, rowptr, csrc, cw, dinv, b4, hB, N);

    // ---- L5: GEMV 64->1, then agg (+b5) into d_out ----
    gemv_kernel<<<cdiv((long long)N * 32, T), T>>>(hB, W5, s1, N, 64);
    agg_csr1_kernel<<<cdiv(N, T), T>>>(s1, rowptr, csrc, cw, dinv, b5, (float*)d_out, N);
}